// round 14
// baseline (speedup 1.0000x reference)
#include <cuda_runtime.h>
#include <cuda_fp16.h>
#include <math_constants.h>
#include <cstdint>

#define BB 4
#define NN 4096
#define DD 256

// ---------------- device scratch (allocation-free rule) ----------------
__device__ __align__(128) __half g_Qhi[(size_t)BB*NN*DD];   // [b][n][d]
__device__ __align__(128) __half g_Qlo[(size_t)BB*NN*DD];
__device__ __align__(128) __half g_Khi[(size_t)BB*NN*DD];   // [b][n][d]
__device__ __align__(128) __half g_Klo[(size_t)BB*NN*DD];
__device__ __align__(128) __half g_Vthi[(size_t)BB*DD*NN];  // [b][d][key]
__device__ __align__(128) __half g_Vtlo[(size_t)BB*DD*NN];
__device__ __align__(128) __half g_Phi[(size_t)BB*NN*NN];   // [b][q][key]  (UNNORMALIZED exp)
__device__ __align__(128) float  g_S [(size_t)BB*NN*NN];    // [b][q][key]
__device__ __align__(128) float  g_invsum[(size_t)BB*NN];   // 1/rowsum

// ---------------- helpers ----------------
__device__ __forceinline__ uint32_t smem_u32(const void* p) {
    uint32_t a;
    asm("{ .reg .u64 t; cvta.to.shared.u64 t, %1; cvt.u32.u64 %0, t; }" : "=r"(a) : "l"(p));
    return a;
}

#define LDM4(r, addr) asm volatile( \
    "ldmatrix.sync.aligned.m8n8.x4.shared.b16 {%0,%1,%2,%3}, [%4];" \
    : "=r"((r)[0]), "=r"((r)[1]), "=r"((r)[2]), "=r"((r)[3]) : "r"(addr))

#define MMA16816F(c, a, b0, b1) asm volatile( \
    "mma.sync.aligned.m16n8k16.row.col.f32.f16.f16.f32 " \
    "{%0,%1,%2,%3}, {%4,%5,%6,%7}, {%8,%9}, {%0,%1,%2,%3};" \
    : "+f"((c)[0]), "+f"((c)[1]), "+f"((c)[2]), "+f"((c)[3]) \
    : "r"((a)[0]), "r"((a)[1]), "r"((a)[2]), "r"((a)[3]), "r"(b0), "r"(b1))

#define CP16(so, ga) asm volatile("cp.async.cg.shared.global [%0], [%1], 16;" \
    :: "r"(so), "l"(ga) : "memory")
#define CP_COMMIT() asm volatile("cp.async.commit_group;" ::: "memory")
#define CP_WAIT1()  asm volatile("cp.async.wait_group 1;" ::: "memory")
#define CP_WAIT2()  asm volatile("cp.async.wait_group 2;" ::: "memory")

// packed f32x2 FMA
#define FFMA2(acc, a, b) asm("fma.rn.f32x2 %0, %1, %2, %0;" : "+l"(acc) : "l"(a), "l"(b))
#define PACK2(dst, lo, hi) asm("mov.b64 %0, {%1, %2};" : "=l"(dst) : "r"(lo), "r"(hi))
#define UNPACK2(lo, hi, src) asm("mov.b64 {%0, %1}, %2;" : "=r"(lo), "=r"(hi) : "l"(src))

// 64B-pitch tile with xor swizzle on 16B chunks
__device__ __forceinline__ uint32_t swz(uint32_t tile, int row, int chunk) {
    return tile + (uint32_t)row * 64u + ((uint32_t)((chunk ^ ((row >> 1) & 3)) & 3) << 4);
}

#define T64_B  4096u
#define T128_B 8192u

// QK: CTA 128x128, stage = 4 x 8KB = 32KB, 3 stages, 256 thr, 2 CTAs/SM
#define QK_STAGE_B 32768u
#define QK_SMEM    (3 * 32768)
// AV: CTA 64d x 64q, stage = Vhi+Vlo+Phi = 3 x 4KB = 12KB, 4 stages, 4 CTAs/SM
#define AV_STAGE_B 12288u
#define AV_SMEM    (4 * 12288)

// ---------------------------------------------------------------------------
// QK: S[128q,128k](fp32) = Q(128,256) . K(128,256)^T, 3-term split-fp16.
// 256 threads, 8 warps (4m x 2n), warp tile 32x64. 2 CTAs/SM. z = 2 batches.
// ---------------------------------------------------------------------------
__global__ __launch_bounds__(256, 2) void qk_kernel(int bbase)
{
    extern __shared__ __align__(128) char sm[];
    const int tid  = threadIdx.x;
    const int lane = tid & 31, wid = tid >> 5;
    const int wm = wid & 3, wn = wid >> 2;
    const int bx = blockIdx.x, by = blockIdx.y;
    const int bz = bbase + blockIdx.z;

    size_t ab = ((size_t)bz * NN + (size_t)by * 128) * DD;
    size_t bb = ((size_t)bz * NN + (size_t)bx * 128) * DD;
    const __half* Ahi = g_Qhi + ab;  const __half* Alo = g_Qlo + ab;
    const __half* Bhi = g_Khi + bb;  const __half* Blo = g_Klo + bb;
    float* C = g_S + (size_t)bz * NN * NN + (size_t)by * 128 * NN + (size_t)bx * 128;

    const uint32_t sbase = smem_u32(sm);

    auto load_stage = [&](int s, int ch) {
        uint32_t st = sbase + (uint32_t)s * QK_STAGE_B;
        size_t k0 = (size_t)ch * 32;
        const __half* gt[4] = { Ahi + k0, Alo + k0, Bhi + k0, Blo + k0 };
        #pragma unroll
        for (int t2 = 0; t2 < 4; ++t2) {
            uint32_t tb = st + (uint32_t)t2 * T128_B;
            #pragma unroll
            for (int i = 0; i < 2; ++i) {
                int id = tid + i * 256;
                int row = id >> 2, c = id & 3;
                CP16(swz(tb, row, c), gt[t2] + (size_t)row * DD + c * 8);
            }
        }
    };

    float accf[2][8][4] = {};

    auto compute = [&](int s) {
        uint32_t st  = sbase + (uint32_t)s * QK_STAGE_B;
        uint32_t tAh = st, tAl = st + T128_B;
        uint32_t tBh = st + 2 * T128_B, tBl = st + 3 * T128_B;
        #pragma unroll
        for (int ks = 0; ks < 2; ++ks) {
            uint32_t ah[2][4], al[2][4];
            const int arow = wm * 32 + (lane & 15);
            const int achk = ks * 2 + (lane >> 4);
            #pragma unroll
            for (int mt = 0; mt < 2; ++mt) {
                LDM4(ah[mt], swz(tAh, arow + mt * 16, achk));
                LDM4(al[mt], swz(tAl, arow + mt * 16, achk));
            }
            const int brow = wn * 64 + ((lane >> 4) << 3) + (lane & 7);
            const int bchk = ks * 2 + ((lane >> 3) & 1);
            #pragma unroll
            for (int nt = 0; nt < 4; ++nt) {
                uint32_t bh4[4], bl4[4];
                LDM4(bh4, swz(tBh, brow + nt * 16, bchk));
                LDM4(bl4, swz(tBl, brow + nt * 16, bchk));
                #pragma unroll
                for (int mt = 0; mt < 2; ++mt) {
                    MMA16816F(accf[mt][nt*2],   ah[mt], bh4[0], bh4[1]);
                    MMA16816F(accf[mt][nt*2],   ah[mt], bl4[0], bl4[1]);
                    MMA16816F(accf[mt][nt*2],   al[mt], bh4[0], bh4[1]);
                    MMA16816F(accf[mt][nt*2+1], ah[mt], bh4[2], bh4[3]);
                    MMA16816F(accf[mt][nt*2+1], ah[mt], bl4[2], bl4[3]);
                    MMA16816F(accf[mt][nt*2+1], al[mt], bh4[2], bh4[3]);
                }
            }
        }
    };

    load_stage(0, 0); CP_COMMIT();
    load_stage(1, 1); CP_COMMIT();

    const int nchunks = DD / 32;  // 8
    for (int ch = 0; ch < nchunks; ++ch) {
        CP_WAIT1();
        __syncthreads();
        if (ch + 2 < nchunks) load_stage((ch + 2) % 3, ch + 2);
        CP_COMMIT();
        compute(ch % 3);
    }

    const int r0 = wm * 32 + (lane >> 2);
    const int c0 = wn * 64 + (lane & 3) * 2;
    #pragma unroll
    for (int mt = 0; mt < 2; ++mt)
        #pragma unroll
        for (int n8 = 0; n8 < 8; ++n8) {
            float* p = C + (size_t)(r0 + mt * 16) * NN + c0 + n8 * 8;
            *(float2*)p            = make_float2(accf[mt][n8][0], accf[mt][n8][1]);
            *(float2*)(p + 8 * NN) = make_float2(accf[mt][n8][2], accf[mt][n8][3]);
        }
}

// ---------------------------------------------------------------------------
// AV: out[64d,64q](fp32) = Vt(64,4096) . P_un(64,4096)^T, scaled by invsum[q].
// 128 threads, 4 warps (2m x 2n), warp tile 32x32. 4 CTAs/SM. z = nb batches.
// ---------------------------------------------------------------------------
__global__ __launch_bounds__(128, 4) void av_kernel(float* __restrict__ outp, int bbase)
{
    extern __shared__ __align__(128) char sm[];
    const int tid  = threadIdx.x;
    const int lane = tid & 31, wid = tid >> 5;
    const int wm = wid & 1, wn = wid >> 1;
    const int bx = blockIdx.x, by = blockIdx.y;
    const int bz = bbase + blockIdx.z;

    size_t ab = (size_t)bz * DD * NN + (size_t)by * 64 * NN;
    size_t bb = (size_t)bz * NN * NN + (size_t)bx * 64 * NN;
    const __half* Ahi = g_Vthi + ab;  const __half* Alo = g_Vtlo + ab;
    const __half* Bhi = g_Phi  + bb;
    float* C = outp + (size_t)bz * DD * NN + (size_t)by * 64 * NN + (size_t)bx * 64;
    const float* isum = g_invsum + (size_t)bz * NN + (size_t)bx * 64;

    const uint32_t sbase = smem_u32(sm);

    auto load_stage = [&](int s, int ch) {
        uint32_t st = sbase + (uint32_t)s * AV_STAGE_B;
        size_t k0 = (size_t)ch * 32;
        const __half* gt[3] = { Ahi + k0, Alo + k0, Bhi + k0 };
        #pragma unroll
        for (int t2 = 0; t2 < 3; ++t2) {
            uint32_t tb = st + (uint32_t)t2 * T64_B;
            #pragma unroll
            for (int i = 0; i < 2; ++i) {
                int id = tid + i * 128;
                int row = id >> 2, c = id & 3;
                CP16(swz(tb, row, c), gt[t2] + (size_t)row * NN + c * 8);
            }
        }
    };

    float accf[2][4][4] = {};

    auto compute = [&](int s) {
        uint32_t st  = sbase + (uint32_t)s * AV_STAGE_B;
        uint32_t tAh = st, tAl = st + T64_B;
        uint32_t tBh = st + 2 * T64_B;
        #pragma unroll
        for (int ks = 0; ks < 2; ++ks) {
            uint32_t ah[2][4], al[2][4];
            const int arow = wm * 32 + (lane & 15);
            const int achk = ks * 2 + (lane >> 4);
            #pragma unroll
            for (int mt = 0; mt < 2; ++mt) {
                LDM4(ah[mt], swz(tAh, arow + mt * 16, achk));
                LDM4(al[mt], swz(tAl, arow + mt * 16, achk));
            }
            const int brow = wn * 32 + ((lane >> 4) << 3) + (lane & 7);
            const int bchk = ks * 2 + ((lane >> 3) & 1);
            #pragma unroll
            for (int nt = 0; nt < 2; ++nt) {
                uint32_t bh4[4];
                LDM4(bh4, swz(tBh, brow + nt * 16, bchk));
                #pragma unroll
                for (int mt = 0; mt < 2; ++mt) {
                    MMA16816F(accf[mt][nt*2],   ah[mt], bh4[0], bh4[1]);  // P*Vhi
                    MMA16816F(accf[mt][nt*2],   al[mt], bh4[0], bh4[1]);  // P*Vlo
                    MMA16816F(accf[mt][nt*2+1], ah[mt], bh4[2], bh4[3]);
                    MMA16816F(accf[mt][nt*2+1], al[mt], bh4[2], bh4[3]);
                }
            }
        }
    };

    load_stage(0, 0); CP_COMMIT();
    load_stage(1, 1); CP_COMMIT();
    load_stage(2, 2); CP_COMMIT();

    const int nchunks = NN / 32;  // 128
    for (int ch = 0; ch < nchunks; ++ch) {
        CP_WAIT2();
        __syncthreads();
        if (ch + 3 < nchunks) load_stage((ch + 3) & 3, ch + 3);
        CP_COMMIT();
        compute(ch & 3);
    }

    const int r0 = wm * 32 + (lane >> 2);
    const int c0 = wn * 32 + (lane & 3) * 2;
    #pragma unroll
    for (int mt = 0; mt < 2; ++mt)
        #pragma unroll
        for (int n8 = 0; n8 < 4; ++n8) {
            float2 iv = *(const float2*)(isum + c0 + n8 * 8);
            float* p = C + (size_t)(r0 + mt * 16) * NN + c0 + n8 * 8;
            *(float2*)p            = make_float2(accf[mt][n8][0] * iv.x, accf[mt][n8][1] * iv.y);
            *(float2*)(p + 8 * NN) = make_float2(accf[mt][n8][2] * iv.x, accf[mt][n8][3] * iv.y);
        }
}

// ---------------------------------------------------------------------------
__device__ __forceinline__ void split8h(const float* v, uint4& uh, uint4& ul) {
    __half2 h[4], l[4];
    #pragma unroll
    for (int j = 0; j < 4; ++j) {
        float a = v[2*j], b = v[2*j+1];
        __half ha = __float2half_rn(a), hb = __float2half_rn(b);
        __half la = __float2half_rn(a - __half2float(ha));
        __half lb = __float2half_rn(b - __half2float(hb));
        h[j] = __halves2half2(ha, hb);
        l[j] = __halves2half2(la, lb);
    }
    uh = *(uint4*)h; ul = *(uint4*)l;
}

// Kernel 1: fused QKV projection (FFMA2), fp16 hi/lo out.
// vmode 0: z in [0, 2*nb) -> b = bbase + z/2, w = z&1 (Q/K).
// vmode 1: z in [0, BB) -> V, all batches.
__global__ __launch_bounds__(256, 2) void proj_kernel(
    int vmode, int bbase,
    const float* __restrict__ x,
    const float* __restrict__ Wq, const float* __restrict__ bq,
    const float* __restrict__ Wk, const float* __restrict__ bk,
    const float* __restrict__ Wv, const float* __restrict__ bv)
{
    __shared__ float As[16][132];
    __shared__ float Bs[16][132];

    const int bzz = blockIdx.z;
    const int b = vmode ? bzz : (bbase + (bzz >> 1));
    const int w = vmode ? 2 : (bzz & 1);
    const float* W    = (w == 0) ? Wq : ((w == 1) ? Wk : Wv);
    const float* bias = (w == 0) ? bq : ((w == 1) ? bk : bv);

    const int m0 = blockIdx.x * 128;
    const int d0 = blockIdx.y * 128;
    const int tid = threadIdx.x;
    const int tx = tid & 15, ty = tid >> 4;
    const float* Abase = x + (size_t)b * DD * NN;

    unsigned long long acc2[8][4];
    #pragma unroll
    for (int i = 0; i < 8; ++i)
        #pragma unroll
        for (int j = 0; j < 4; ++j) acc2[i][j] = 0ull;

    float4 pa[2], pb[2];
    #pragma unroll
    for (int u = 0; u < 2; ++u) {
        int idx = tid + u * 256;
        int kl = idx >> 5, m4 = (idx & 31) << 2;
        pa[u] = *(const float4*)(Abase + (size_t)kl * NN + m0 + m4);
        pb[u] = *(const float4*)(W     + (size_t)kl * DD + d0 + m4);
    }
    for (int kc = 0; kc < DD; kc += 16) {
        #pragma unroll
        for (int u = 0; u < 2; ++u) {
            int idx = tid + u * 256;
            int kl = idx >> 5, m4 = (idx & 31) << 2;
            *(float4*)&As[kl][m4] = pa[u];
            *(float4*)&Bs[kl][m4] = pb[u];
        }
        __syncthreads();
        if (kc + 16 < DD) {
            int kn = kc + 16;
            #pragma unroll
            for (int u = 0; u < 2; ++u) {
                int idx = tid + u * 256;
                int kl = idx >> 5, m4 = (idx & 31) << 2;
                pa[u] = *(const float4*)(Abase + (size_t)(kn + kl) * NN + m0 + m4);
                pb[u] = *(const float4*)(W     + (size_t)(kn + kl) * DD + d0 + m4);
            }
        }
        #pragma unroll
        for (int kk = 0; kk < 16; ++kk) {
            float a[8], bb[8];
            *(float4*)&a[0]  = *(float4*)&As[kk][ty * 8];
            *(float4*)&a[4]  = *(float4*)&As[kk][ty * 8 + 4];
            *(float4*)&bb[0] = *(float4*)&Bs[kk][tx * 8];
            *(float4*)&bb[4] = *(float4*)&Bs[kk][tx * 8 + 4];
            unsigned long long b2[4];
            #pragma unroll
            for (int j = 0; j < 4; ++j)
                PACK2(b2[j], __float_as_uint(bb[2*j]), __float_as_uint(bb[2*j+1]));
            #pragma unroll
            for (int i = 0; i < 8; ++i) {
                unsigned long long a2;
                PACK2(a2, __float_as_uint(a[i]), __float_as_uint(a[i]));
                #pragma unroll
                for (int j = 0; j < 4; ++j)
                    FFMA2(acc2[i][j], a2, b2[j]);
            }
        }
        __syncthreads();
    }

    float acc[8][8];
    #pragma unroll
    for (int i = 0; i < 8; ++i)
        #pragma unroll
        for (int j = 0; j < 4; ++j) {
            uint32_t lo, hi;
            UNPACK2(lo, hi, acc2[i][j]);
            acc[i][2*j]   = __uint_as_float(lo);
            acc[i][2*j+1] = __uint_as_float(hi);
        }

    if (w < 2) {  // Q/K row-major [n][d]
        __half* Oh = ((w == 0) ? g_Qhi : g_Khi) + (size_t)b * NN * DD;
        __half* Ol = ((w == 0) ? g_Qlo : g_Klo) + (size_t)b * NN * DD;
        #pragma unroll
        for (int i = 0; i < 8; ++i) {
            int n = m0 + ty * 8 + i, d = d0 + tx * 8;
            float v[8];
            #pragma unroll
            for (int j = 0; j < 8; ++j) v[j] = acc[i][j] + bias[d + j];
            uint4 uh, ul; split8h(v, uh, ul);
            *(uint4*)(Oh + (size_t)n * DD + d) = uh;
            *(uint4*)(Ol + (size_t)n * DD + d) = ul;
        }
    } else {      // V transposed [d][n]
        __half* Oh = g_Vthi + (size_t)b * DD * NN;
        __half* Ol = g_Vtlo + (size_t)b * DD * NN;
        #pragma unroll
        for (int j = 0; j < 8; ++j) {
            int d = d0 + tx * 8 + j;
            float bb = bias[d];
            float v[8];
            #pragma unroll
            for (int i = 0; i < 8; ++i) v[i] = acc[i][j] + bb;
            uint4 uh, ul; split8h(v, uh, ul);
            *(uint4*)(Oh + (size_t)d * NN + m0 + ty * 8) = uh;
            *(uint4*)(Ol + (size_t)d * NN + m0 + ty * 8) = ul;
        }
    }
}

// Kernel 3: row softmax, fp32 S in, UNNORMALIZED fp16 exp out + invsum.
__inline__ __device__ float warpMax(float v) {
    #pragma unroll
    for (int o = 16; o; o >>= 1) v = fmaxf(v, __shfl_xor_sync(0xffffffffu, v, o));
    return v;
}
__inline__ __device__ float warpSum(float v) {
    #pragma unroll
    for (int o = 16; o; o >>= 1) v += __shfl_xor_sync(0xffffffffu, v, o);
    return v;
}

__global__ __launch_bounds__(256) void softmax_kernel(int bbase)
{
    __shared__ float red[8];
    const size_t row = (size_t)bbase * NN + blockIdx.x;
    const float* p = g_S + row * (size_t)NN;
    __half* ph = g_Phi + row * (size_t)NN;
    const int tid = threadIdx.x;
    const int lane = tid & 31, wid = tid >> 5;

    float4 v[4];
    float m = -CUDART_INF_F;
    #pragma unroll
    for (int u = 0; u < 4; ++u) {
        v[u] = *(const float4*)(p + (size_t)(tid + u * 256) * 4);
        m = fmaxf(m, fmaxf(fmaxf(v[u].x, v[u].y), fmaxf(v[u].z, v[u].w)));
    }
    m = warpMax(m);
    if (lane == 0) red[wid] = m;
    __syncthreads();
    float bm = red[0];
    #pragma unroll
    for (int i = 1; i < 8; ++i) bm = fmaxf(bm, red[i]);
    __syncthreads();

    float s = 0.f;
    #pragma unroll
    for (int u = 0; u < 4; ++u) {
        v[u].x = __expf(v[u].x - bm); v[u].y = __expf(v[u].y - bm);
        v[u].z = __expf(v[u].z - bm); v[u].w = __expf(v[u].w - bm);
        s += v[u].x + v[u].y + v[u].z + v[u].w;
    }
    s = warpSum(s);
    if (lane == 0) red[wid] = s;
    __syncthreads();
    float tot = 0.f;
    #pragma unroll
    for (int i = 0; i < 8; ++i) tot += red[i];
    if (tid == 0) g_invsum[row] = 1.0f / tot;

    #pragma unroll
    for (int u = 0; u < 4; ++u) {
        size_t idx = (size_t)(tid + u * 256) * 4;
        *(__half2*)(ph + idx)     = __halves2half2(__float2half_rn(v[u].x),
                                                   __float2half_rn(v[u].y));
        *(__half2*)(ph + idx + 2) = __halves2half2(__float2half_rn(v[u].z),
                                                   __float2half_rn(v[u].w));
    }
}

// ---------------------------------------------------------------------------
extern "C" void kernel_launch(void* const* d_in, const int* in_sizes, int n_in,
                              void* d_out, int out_size)
{
    const float* x  = (const float*)d_in[0];
    const float* Wq = (const float*)d_in[1];
    const float* bq = (const float*)d_in[2];
    const float* Wk = (const float*)d_in[3];
    const float* bk = (const float*)d_in[4];
    const float* Wv = (const float*)d_in[5];
    const float* bv = (const float*)d_in[6];
    float* out = (float*)d_out;

    static cudaStream_t s2 = nullptr;
    static cudaEvent_t eRoot, eP1, eQ0, eQ1, eS1, eA0;
    if (!s2) {
        cudaStreamCreateWithFlags(&s2, cudaStreamNonBlocking);
        cudaEventCreateWithFlags(&eRoot, cudaEventDisableTiming);
        cudaEventCreateWithFlags(&eP1, cudaEventDisableTiming);
        cudaEventCreateWithFlags(&eQ0, cudaEventDisableTiming);
        cudaEventCreateWithFlags(&eQ1, cudaEventDisableTiming);
        cudaEventCreateWithFlags(&eS1, cudaEventDisableTiming);
        cudaEventCreateWithFlags(&eA0, cudaEventDisableTiming);
        cudaFuncSetAttribute(qk_kernel, cudaFuncAttributeMaxDynamicSharedMemorySize, QK_SMEM);
        cudaFuncSetAttribute(av_kernel, cudaFuncAttributeMaxDynamicSharedMemorySize, AV_SMEM);
    }

    // Fork s2 FROM the capture origin first so all s2 events are captured.
    cudaEventRecord(eRoot, 0);
    cudaStreamWaitEvent(s2, eRoot, 0);

    // s2: projV(all) -> projQK(g1)[eP1] -> (wait eQ0) softmax(g0) -> AV(g0)[eA0]
    //     -> (wait eQ1) softmax(g1)[eS1]
    // s0: projQK(g0) -> QK(g0)[eQ0] -> (wait eP1) QK(g1)[eQ1]
    //     -> (wait eS1) AV(g1) -> (wait eA0) done
    proj_kernel<<<dim3(NN / 128, DD / 128, BB), 256, 0, s2>>>(1, 0, x, Wq, bq, Wk, bk, Wv, bv);
    proj_kernel<<<dim3(NN / 128, DD / 128, 4), 256, 0, s2>>>(0, 2, x, Wq, bq, Wk, bk, Wv, bv);
    cudaEventRecord(eP1, s2);

    proj_kernel<<<dim3(NN / 128, DD / 128, 4), 256>>>(0, 0, x, Wq, bq, Wk, bk, Wv, bv);
    qk_kernel<<<dim3(NN / 128, NN / 128, 2), 256, QK_SMEM>>>(0);
    cudaEventRecord(eQ0, 0);
    cudaStreamWaitEvent(0, eP1, 0);
    qk_kernel<<<dim3(NN / 128, NN / 128, 2), 256, QK_SMEM>>>(2);
    cudaEventRecord(eQ1, 0);

    cudaStreamWaitEvent(s2, eQ0, 0);
    softmax_kernel<<<2 * NN, 256, 0, s2>>>(0);
    av_kernel<<<dim3(NN / 64, DD / 64, 2), 128, AV_SMEM, s2>>>(out, 0);
    cudaEventRecord(eA0, s2);
    cudaStreamWaitEvent(s2, eQ1, 0);
    softmax_kernel<<<2 * NN, 256, 0, s2>>>(2);
    cudaEventRecord(eS1, s2);

    cudaStreamWaitEvent(0, eS1, 0);
    av_kernel<<<dim3(NN / 64, DD / 64, 2), 128, AV_SMEM>>>(out, 2);
    cudaStreamWaitEvent(0, eA0, 0);
}

// round 15
// speedup vs baseline: 1.1387x; 1.1387x over previous
#include <cuda_runtime.h>
#include <cuda_fp16.h>
#include <math_constants.h>
#include <cstdint>

#define BB 4
#define NN 4096
#define DD 256

// ---------------- device scratch (allocation-free rule) ----------------
__device__ __align__(128) __half g_Qhi[(size_t)BB*NN*DD];   // [b][n][d]
__device__ __align__(128) __half g_Qlo[(size_t)BB*NN*DD];
__device__ __align__(128) __half g_Khi[(size_t)BB*NN*DD];   // [b][n][d]
__device__ __align__(128) __half g_Klo[(size_t)BB*NN*DD];
__device__ __align__(128) __half g_Vthi[(size_t)BB*DD*NN];  // [b][d][key]
__device__ __align__(128) __half g_Phi[(size_t)BB*NN*NN];   // [b][q][key]  (UNNORMALIZED exp)
__device__ __align__(128) float  g_S [(size_t)BB*NN*NN];    // [b][q][key]
__device__ __align__(128) float  g_invsum[(size_t)BB*NN];   // 1/rowsum

// ---------------- helpers ----------------
__device__ __forceinline__ uint32_t smem_u32(const void* p) {
    uint32_t a;
    asm("{ .reg .u64 t; cvta.to.shared.u64 t, %1; cvt.u32.u64 %0, t; }" : "=r"(a) : "l"(p));
    return a;
}

#define LDM4(r, addr) asm volatile( \
    "ldmatrix.sync.aligned.m8n8.x4.shared.b16 {%0,%1,%2,%3}, [%4];" \
    : "=r"((r)[0]), "=r"((r)[1]), "=r"((r)[2]), "=r"((r)[3]) : "r"(addr))

#define MMA16816F(c, a, b0, b1) asm volatile( \
    "mma.sync.aligned.m16n8k16.row.col.f32.f16.f16.f32 " \
    "{%0,%1,%2,%3}, {%4,%5,%6,%7}, {%8,%9}, {%0,%1,%2,%3};" \
    : "+f"((c)[0]), "+f"((c)[1]), "+f"((c)[2]), "+f"((c)[3]) \
    : "r"((a)[0]), "r"((a)[1]), "r"((a)[2]), "r"((a)[3]), "r"(b0), "r"(b1))

#define CP16(so, ga) asm volatile("cp.async.cg.shared.global [%0], [%1], 16;" \
    :: "r"(so), "l"(ga) : "memory")
#define CP_COMMIT() asm volatile("cp.async.commit_group;" ::: "memory")
#define CP_WAIT1()  asm volatile("cp.async.wait_group 1;" ::: "memory")
#define CP_WAIT2()  asm volatile("cp.async.wait_group 2;" ::: "memory")

// packed f32x2 FMA
#define FFMA2(acc, a, b) asm("fma.rn.f32x2 %0, %1, %2, %0;" : "+l"(acc) : "l"(a), "l"(b))
#define PACK2(dst, lo, hi) asm("mov.b64 %0, {%1, %2};" : "=l"(dst) : "r"(lo), "r"(hi))
#define UNPACK2(lo, hi, src) asm("mov.b64 {%0, %1}, %2;" : "=r"(lo), "=r"(hi) : "l"(src))

// 64B-pitch tile with xor swizzle on 16B chunks
__device__ __forceinline__ uint32_t swz(uint32_t tile, int row, int chunk) {
    return tile + (uint32_t)row * 64u + ((uint32_t)((chunk ^ ((row >> 1) & 3)) & 3) << 4);
}

#define T64_B  4096u
#define T128_B 8192u

// QK: CTA 128x128, stage = 4 x 8KB = 32KB, 3 stages, 256 thr, 2 CTAs/SM
#define QK_STAGE_B 32768u
#define QK_SMEM    (3 * 32768)
// AV: CTA 64d x 64q, stage = Vhi+Phi = 2 x 4KB = 8KB, 4 stages, 4 CTAs/SM
#define AV_STAGE_B 8192u
#define AV_SMEM    (4 * 8192)

// ---------------------------------------------------------------------------
// QK: S[128q,128k](fp32) = Q(128,256) . K(128,256)^T, 3-term split-fp16.
// 256 threads, 8 warps (4m x 2n), warp tile 32x64. 2 CTAs/SM. z = 2 batches.
// ---------------------------------------------------------------------------
__global__ __launch_bounds__(256, 2) void qk_kernel(int bbase)
{
    extern __shared__ __align__(128) char sm[];
    const int tid  = threadIdx.x;
    const int lane = tid & 31, wid = tid >> 5;
    const int wm = wid & 3, wn = wid >> 2;
    const int bx = blockIdx.x, by = blockIdx.y;
    const int bz = bbase + blockIdx.z;

    size_t ab = ((size_t)bz * NN + (size_t)by * 128) * DD;
    size_t bb = ((size_t)bz * NN + (size_t)bx * 128) * DD;
    const __half* Ahi = g_Qhi + ab;  const __half* Alo = g_Qlo + ab;
    const __half* Bhi = g_Khi + bb;  const __half* Blo = g_Klo + bb;
    float* C = g_S + (size_t)bz * NN * NN + (size_t)by * 128 * NN + (size_t)bx * 128;

    const uint32_t sbase = smem_u32(sm);

    auto load_stage = [&](int s, int ch) {
        uint32_t st = sbase + (uint32_t)s * QK_STAGE_B;
        size_t k0 = (size_t)ch * 32;
        const __half* gt[4] = { Ahi + k0, Alo + k0, Bhi + k0, Blo + k0 };
        #pragma unroll
        for (int t2 = 0; t2 < 4; ++t2) {
            uint32_t tb = st + (uint32_t)t2 * T128_B;
            #pragma unroll
            for (int i = 0; i < 2; ++i) {
                int id = tid + i * 256;
                int row = id >> 2, c = id & 3;
                CP16(swz(tb, row, c), gt[t2] + (size_t)row * DD + c * 8);
            }
        }
    };

    float accf[2][8][4] = {};

    auto compute = [&](int s) {
        uint32_t st  = sbase + (uint32_t)s * QK_STAGE_B;
        uint32_t tAh = st, tAl = st + T128_B;
        uint32_t tBh = st + 2 * T128_B, tBl = st + 3 * T128_B;
        #pragma unroll
        for (int ks = 0; ks < 2; ++ks) {
            uint32_t ah[2][4], al[2][4];
            const int arow = wm * 32 + (lane & 15);
            const int achk = ks * 2 + (lane >> 4);
            #pragma unroll
            for (int mt = 0; mt < 2; ++mt) {
                LDM4(ah[mt], swz(tAh, arow + mt * 16, achk));
                LDM4(al[mt], swz(tAl, arow + mt * 16, achk));
            }
            const int brow = wn * 64 + ((lane >> 4) << 3) + (lane & 7);
            const int bchk = ks * 2 + ((lane >> 3) & 1);
            #pragma unroll
            for (int nt = 0; nt < 4; ++nt) {
                uint32_t bh4[4], bl4[4];
                LDM4(bh4, swz(tBh, brow + nt * 16, bchk));
                LDM4(bl4, swz(tBl, brow + nt * 16, bchk));
                #pragma unroll
                for (int mt = 0; mt < 2; ++mt) {
                    MMA16816F(accf[mt][nt*2],   ah[mt], bh4[0], bh4[1]);
                    MMA16816F(accf[mt][nt*2],   ah[mt], bl4[0], bl4[1]);
                    MMA16816F(accf[mt][nt*2],   al[mt], bh4[0], bh4[1]);
                    MMA16816F(accf[mt][nt*2+1], ah[mt], bh4[2], bh4[3]);
                    MMA16816F(accf[mt][nt*2+1], ah[mt], bl4[2], bl4[3]);
                    MMA16816F(accf[mt][nt*2+1], al[mt], bh4[2], bh4[3]);
                }
            }
        }
    };

    load_stage(0, 0); CP_COMMIT();
    load_stage(1, 1); CP_COMMIT();

    const int nchunks = DD / 32;  // 8
    for (int ch = 0; ch < nchunks; ++ch) {
        CP_WAIT1();
        __syncthreads();
        if (ch + 2 < nchunks) load_stage((ch + 2) % 3, ch + 2);
        CP_COMMIT();
        compute(ch % 3);
    }

    const int r0 = wm * 32 + (lane >> 2);
    const int c0 = wn * 64 + (lane & 3) * 2;
    #pragma unroll
    for (int mt = 0; mt < 2; ++mt)
        #pragma unroll
        for (int n8 = 0; n8 < 8; ++n8) {
            float* p = C + (size_t)(r0 + mt * 16) * NN + c0 + n8 * 8;
            *(float2*)p            = make_float2(accf[mt][n8][0], accf[mt][n8][1]);
            *(float2*)(p + 8 * NN) = make_float2(accf[mt][n8][2], accf[mt][n8][3]);
        }
}

// ---------------------------------------------------------------------------
// AV: out[64d,64q](fp32) = Vhi(64,4096) . P_un(64,4096)^T, scaled by invsum[q].
// SINGLE term (V fp16-only). 128 threads, 4 warps (2m x 2n), warp tile 32x32.
// 4 CTAs/SM, 1024 CTAs.
// ---------------------------------------------------------------------------
__global__ __launch_bounds__(128, 4) void av_kernel(float* __restrict__ outp, int bbase)
{
    extern __shared__ __align__(128) char sm[];
    const int tid  = threadIdx.x;
    const int lane = tid & 31, wid = tid >> 5;
    const int wm = wid & 1, wn = wid >> 1;
    const int bx = blockIdx.x, by = blockIdx.y;
    const int bz = bbase + blockIdx.z;

    size_t ab = (size_t)bz * DD * NN + (size_t)by * 64 * NN;
    size_t bb = (size_t)bz * NN * NN + (size_t)bx * 64 * NN;
    const __half* Ahi = g_Vthi + ab;
    const __half* Bhi = g_Phi  + bb;
    float* C = outp + (size_t)bz * DD * NN + (size_t)by * 64 * NN + (size_t)bx * 64;
    const float* isum = g_invsum + (size_t)bz * NN + (size_t)bx * 64;

    const uint32_t sbase = smem_u32(sm);

    auto load_stage = [&](int s, int ch) {
        uint32_t st = sbase + (uint32_t)s * AV_STAGE_B;
        size_t k0 = (size_t)ch * 32;
        const __half* gt[2] = { Ahi + k0, Bhi + k0 };
        #pragma unroll
        for (int t2 = 0; t2 < 2; ++t2) {
            uint32_t tb = st + (uint32_t)t2 * T64_B;
            #pragma unroll
            for (int i = 0; i < 2; ++i) {
                int id = tid + i * 128;
                int row = id >> 2, c = id & 3;
                CP16(swz(tb, row, c), gt[t2] + (size_t)row * NN + c * 8);
            }
        }
    };

    float accf[2][4][4] = {};

    auto compute = [&](int s) {
        uint32_t st  = sbase + (uint32_t)s * AV_STAGE_B;
        uint32_t tAh = st;
        uint32_t tBh = st + T64_B;
        #pragma unroll
        for (int ks = 0; ks < 2; ++ks) {
            uint32_t ah[2][4];
            const int arow = wm * 32 + (lane & 15);
            const int achk = ks * 2 + (lane >> 4);
            #pragma unroll
            for (int mt = 0; mt < 2; ++mt)
                LDM4(ah[mt], swz(tAh, arow + mt * 16, achk));
            const int brow = wn * 32 + ((lane >> 4) << 3) + (lane & 7);
            const int bchk = ks * 2 + ((lane >> 3) & 1);
            #pragma unroll
            for (int nt = 0; nt < 2; ++nt) {
                uint32_t bh4[4];
                LDM4(bh4, swz(tBh, brow + nt * 16, bchk));
                #pragma unroll
                for (int mt = 0; mt < 2; ++mt) {
                    MMA16816F(accf[mt][nt*2],   ah[mt], bh4[0], bh4[1]);
                    MMA16816F(accf[mt][nt*2+1], ah[mt], bh4[2], bh4[3]);
                }
            }
        }
    };

    load_stage(0, 0); CP_COMMIT();
    load_stage(1, 1); CP_COMMIT();
    load_stage(2, 2); CP_COMMIT();

    const int nchunks = NN / 32;  // 128
    for (int ch = 0; ch < nchunks; ++ch) {
        CP_WAIT2();
        __syncthreads();
        if (ch + 3 < nchunks) load_stage((ch + 3) & 3, ch + 3);
        CP_COMMIT();
        compute(ch & 3);
    }

    const int r0 = wm * 32 + (lane >> 2);
    const int c0 = wn * 32 + (lane & 3) * 2;
    #pragma unroll
    for (int mt = 0; mt < 2; ++mt)
        #pragma unroll
        for (int n8 = 0; n8 < 4; ++n8) {
            float2 iv = *(const float2*)(isum + c0 + n8 * 8);
            float* p = C + (size_t)(r0 + mt * 16) * NN + c0 + n8 * 8;
            *(float2*)p            = make_float2(accf[mt][n8][0] * iv.x, accf[mt][n8][1] * iv.y);
            *(float2*)(p + 8 * NN) = make_float2(accf[mt][n8][2] * iv.x, accf[mt][n8][3] * iv.y);
        }
}

// ---------------------------------------------------------------------------
__device__ __forceinline__ void split8h(const float* v, uint4& uh, uint4& ul) {
    __half2 h[4], l[4];
    #pragma unroll
    for (int j = 0; j < 4; ++j) {
        float a = v[2*j], b = v[2*j+1];
        __half ha = __float2half_rn(a), hb = __float2half_rn(b);
        __half la = __float2half_rn(a - __half2float(ha));
        __half lb = __float2half_rn(b - __half2float(hb));
        h[j] = __halves2half2(ha, hb);
        l[j] = __halves2half2(la, lb);
    }
    uh = *(uint4*)h; ul = *(uint4*)l;
}

// Kernel 1: fused QKV projection (FFMA2), fp16 out.
// vmode 0: z in [0, 2*BB) -> Q/K hi+lo.  vmode 1: z in [0, BB) -> V hi only.
__global__ __launch_bounds__(256, 2) void proj_kernel(
    int vmode, int bbase,
    const float* __restrict__ x,
    const float* __restrict__ Wq, const float* __restrict__ bq,
    const float* __restrict__ Wk, const float* __restrict__ bk,
    const float* __restrict__ Wv, const float* __restrict__ bv)
{
    __shared__ float As[16][132];
    __shared__ float Bs[16][132];

    const int bzz = blockIdx.z;
    const int b = vmode ? bzz : (bbase + (bzz >> 1));
    const int w = vmode ? 2 : (bzz & 1);
    const float* W    = (w == 0) ? Wq : ((w == 1) ? Wk : Wv);
    const float* bias = (w == 0) ? bq : ((w == 1) ? bk : bv);

    const int m0 = blockIdx.x * 128;
    const int d0 = blockIdx.y * 128;
    const int tid = threadIdx.x;
    const int tx = tid & 15, ty = tid >> 4;
    const float* Abase = x + (size_t)b * DD * NN;

    unsigned long long acc2[8][4];
    #pragma unroll
    for (int i = 0; i < 8; ++i)
        #pragma unroll
        for (int j = 0; j < 4; ++j) acc2[i][j] = 0ull;

    float4 pa[2], pb[2];
    #pragma unroll
    for (int u = 0; u < 2; ++u) {
        int idx = tid + u * 256;
        int kl = idx >> 5, m4 = (idx & 31) << 2;
        pa[u] = *(const float4*)(Abase + (size_t)kl * NN + m0 + m4);
        pb[u] = *(const float4*)(W     + (size_t)kl * DD + d0 + m4);
    }
    for (int kc = 0; kc < DD; kc += 16) {
        #pragma unroll
        for (int u = 0; u < 2; ++u) {
            int idx = tid + u * 256;
            int kl = idx >> 5, m4 = (idx & 31) << 2;
            *(float4*)&As[kl][m4] = pa[u];
            *(float4*)&Bs[kl][m4] = pb[u];
        }
        __syncthreads();
        if (kc + 16 < DD) {
            int kn = kc + 16;
            #pragma unroll
            for (int u = 0; u < 2; ++u) {
                int idx = tid + u * 256;
                int kl = idx >> 5, m4 = (idx & 31) << 2;
                pa[u] = *(const float4*)(Abase + (size_t)(kn + kl) * NN + m0 + m4);
                pb[u] = *(const float4*)(W     + (size_t)(kn + kl) * DD + d0 + m4);
            }
        }
        #pragma unroll
        for (int kk = 0; kk < 16; ++kk) {
            float a[8], bb[8];
            *(float4*)&a[0]  = *(float4*)&As[kk][ty * 8];
            *(float4*)&a[4]  = *(float4*)&As[kk][ty * 8 + 4];
            *(float4*)&bb[0] = *(float4*)&Bs[kk][tx * 8];
            *(float4*)&bb[4] = *(float4*)&Bs[kk][tx * 8 + 4];
            unsigned long long b2[4];
            #pragma unroll
            for (int j = 0; j < 4; ++j)
                PACK2(b2[j], __float_as_uint(bb[2*j]), __float_as_uint(bb[2*j+1]));
            #pragma unroll
            for (int i = 0; i < 8; ++i) {
                unsigned long long a2;
                PACK2(a2, __float_as_uint(a[i]), __float_as_uint(a[i]));
                #pragma unroll
                for (int j = 0; j < 4; ++j)
                    FFMA2(acc2[i][j], a2, b2[j]);
            }
        }
        __syncthreads();
    }

    float acc[8][8];
    #pragma unroll
    for (int i = 0; i < 8; ++i)
        #pragma unroll
        for (int j = 0; j < 4; ++j) {
            uint32_t lo, hi;
            UNPACK2(lo, hi, acc2[i][j]);
            acc[i][2*j]   = __uint_as_float(lo);
            acc[i][2*j+1] = __uint_as_float(hi);
        }

    if (w < 2) {  // Q/K row-major [n][d], hi+lo
        __half* Oh = ((w == 0) ? g_Qhi : g_Khi) + (size_t)b * NN * DD;
        __half* Ol = ((w == 0) ? g_Qlo : g_Klo) + (size_t)b * NN * DD;
        #pragma unroll
        for (int i = 0; i < 8; ++i) {
            int n = m0 + ty * 8 + i, d = d0 + tx * 8;
            float v[8];
            #pragma unroll
            for (int j = 0; j < 8; ++j) v[j] = acc[i][j] + bias[d + j];
            uint4 uh, ul; split8h(v, uh, ul);
            *(uint4*)(Oh + (size_t)n * DD + d) = uh;
            *(uint4*)(Ol + (size_t)n * DD + d) = ul;
        }
    } else {      // V transposed [d][n], hi only
        __half* Oh = g_Vthi + (size_t)b * DD * NN;
        #pragma unroll
        for (int j = 0; j < 8; ++j) {
            int d = d0 + tx * 8 + j;
            float bb = bias[d];
            __half2 hv[4];
            #pragma unroll
            for (int i = 0; i < 4; ++i)
                hv[i] = __halves2half2(__float2half_rn(acc[2*i][j] + bb),
                                       __float2half_rn(acc[2*i+1][j] + bb));
            *(uint4*)(Oh + (size_t)d * NN + m0 + ty * 8) = *(uint4*)hv;
        }
    }
}

// Kernel 3: row softmax, fp32 S in, UNNORMALIZED fp16 exp out + invsum.
__inline__ __device__ float warpMax(float v) {
    #pragma unroll
    for (int o = 16; o; o >>= 1) v = fmaxf(v, __shfl_xor_sync(0xffffffffu, v, o));
    return v;
}
__inline__ __device__ float warpSum(float v) {
    #pragma unroll
    for (int o = 16; o; o >>= 1) v += __shfl_xor_sync(0xffffffffu, v, o);
    return v;
}

__global__ __launch_bounds__(256) void softmax_kernel(int bbase)
{
    __shared__ float red[8];
    const size_t row = (size_t)bbase * NN + blockIdx.x;
    const float* p = g_S + row * (size_t)NN;
    __half* ph = g_Phi + row * (size_t)NN;
    const int tid = threadIdx.x;
    const int lane = tid & 31, wid = tid >> 5;

    float4 v[4];
    float m = -CUDART_INF_F;
    #pragma unroll
    for (int u = 0; u < 4; ++u) {
        v[u] = *(const float4*)(p + (size_t)(tid + u * 256) * 4);
        m = fmaxf(m, fmaxf(fmaxf(v[u].x, v[u].y), fmaxf(v[u].z, v[u].w)));
    }
    m = warpMax(m);
    if (lane == 0) red[wid] = m;
    __syncthreads();
    float bm = red[0];
    #pragma unroll
    for (int i = 1; i < 8; ++i) bm = fmaxf(bm, red[i]);
    __syncthreads();

    float s = 0.f;
    #pragma unroll
    for (int u = 0; u < 4; ++u) {
        v[u].x = __expf(v[u].x - bm); v[u].y = __expf(v[u].y - bm);
        v[u].z = __expf(v[u].z - bm); v[u].w = __expf(v[u].w - bm);
        s += v[u].x + v[u].y + v[u].z + v[u].w;
    }
    s = warpSum(s);
    if (lane == 0) red[wid] = s;
    __syncthreads();
    float tot = 0.f;
    #pragma unroll
    for (int i = 0; i < 8; ++i) tot += red[i];
    if (tid == 0) g_invsum[row] = 1.0f / tot;

    #pragma unroll
    for (int u = 0; u < 4; ++u) {
        size_t idx = (size_t)(tid + u * 256) * 4;
        *(__half2*)(ph + idx)     = __halves2half2(__float2half_rn(v[u].x),
                                                   __float2half_rn(v[u].y));
        *(__half2*)(ph + idx + 2) = __halves2half2(__float2half_rn(v[u].z),
                                                   __float2half_rn(v[u].w));
    }
}

// ---------------------------------------------------------------------------
extern "C" void kernel_launch(void* const* d_in, const int* in_sizes, int n_in,
                              void* d_out, int out_size)
{
    const float* x  = (const float*)d_in[0];
    const float* Wq = (const float*)d_in[1];
    const float* bq = (const float*)d_in[2];
    const float* Wk = (const float*)d_in[3];
    const float* bk = (const float*)d_in[4];
    const float* Wv = (const float*)d_in[5];
    const float* bv = (const float*)d_in[6];
    float* out = (float*)d_out;

    static cudaStream_t s2 = nullptr;
    static cudaEvent_t eRoot, eQ0, eQ1, eS1;
    if (!s2) {
        cudaStreamCreateWithFlags(&s2, cudaStreamNonBlocking);
        cudaEventCreateWithFlags(&eRoot, cudaEventDisableTiming);
        cudaEventCreateWithFlags(&eQ0, cudaEventDisableTiming);
        cudaEventCreateWithFlags(&eQ1, cudaEventDisableTiming);
        cudaEventCreateWithFlags(&eS1, cudaEventDisableTiming);
        cudaFuncSetAttribute(qk_kernel, cudaFuncAttributeMaxDynamicSharedMemorySize, QK_SMEM);
        cudaFuncSetAttribute(av_kernel, cudaFuncAttributeMaxDynamicSharedMemorySize, AV_SMEM);
    }

    // Legal fork: s2 joins capture via eRoot before any s2 work/events.
    cudaEventRecord(eRoot, 0);
    cudaStreamWaitEvent(s2, eRoot, 0);

    // s2: projV -> (wait eQ0) softmax(g0) -> (wait eQ1) softmax(g1)[eS1]
    // s0: projQK(all) -> QK(g0)[eQ0] -> QK(g1)[eQ1] -> (wait eS1) AV(all)
    proj_kernel<<<dim3(NN / 128, DD / 128, BB), 256, 0, s2>>>(1, 0, x, Wq, bq, Wk, bk, Wv, bv);

    proj_kernel<<<dim3(NN / 128, DD / 128, 2 * BB), 256>>>(0, 0, x, Wq, bq, Wk, bk, Wv, bv);
    qk_kernel<<<dim3(NN / 128, NN / 128, 2), 256, QK_SMEM>>>(0);
    cudaEventRecord(eQ0, 0);
    qk_kernel<<<dim3(NN / 128, NN / 128, 2), 256, QK_SMEM>>>(2);
    cudaEventRecord(eQ1, 0);

    cudaStreamWaitEvent(s2, eQ0, 0);
    softmax_kernel<<<2 * NN, 256, 0, s2>>>(0);
    cudaStreamWaitEvent(s2, eQ1, 0);
    softmax_kernel<<<2 * NN, 256, 0, s2>>>(2);
    cudaEventRecord(eS1, s2);

    cudaStreamWaitEvent(0, eS1, 0);
    av_kernel<<<dim3(NN / 64, DD / 64, BB), 128, AV_SMEM>>>(out, 0);
}

// round 16
// speedup vs baseline: 1.1559x; 1.0151x over previous
#include <cuda_runtime.h>
#include <cuda_fp16.h>
#include <math_constants.h>
#include <cstdint>

#define BB 4
#define NN 4096
#define DD 256

// ---------------- device scratch (allocation-free rule) ----------------
__device__ __align__(128) __half g_Qhi[(size_t)BB*NN*DD];   // [b][n][d]
__device__ __align__(128) __half g_Qlo[(size_t)BB*NN*DD];
__device__ __align__(128) __half g_Khi[(size_t)BB*NN*DD];   // [b][n][d]
__device__ __align__(128) __half g_Klo[(size_t)BB*NN*DD];
__device__ __align__(128) __half g_Vthi[(size_t)BB*DD*NN];  // [b][d][key]
__device__ __align__(128) __half g_Phi[(size_t)BB*NN*NN];   // [b][q][key]  (UNNORMALIZED exp)
__device__ __align__(128) float  g_S [(size_t)BB*NN*NN];    // [b][q][key]
__device__ __align__(128) float  g_invsum[(size_t)BB*NN];   // 1/rowsum

// ---------------- helpers ----------------
__device__ __forceinline__ uint32_t smem_u32(const void* p) {
    uint32_t a;
    asm("{ .reg .u64 t; cvta.to.shared.u64 t, %1; cvt.u32.u64 %0, t; }" : "=r"(a) : "l"(p));
    return a;
}

#define LDM4(r, addr) asm volatile( \
    "ldmatrix.sync.aligned.m8n8.x4.shared.b16 {%0,%1,%2,%3}, [%4];" \
    : "=r"((r)[0]), "=r"((r)[1]), "=r"((r)[2]), "=r"((r)[3]) : "r"(addr))

#define MMA16816F(c, a, b0, b1) asm volatile( \
    "mma.sync.aligned.m16n8k16.row.col.f32.f16.f16.f32 " \
    "{%0,%1,%2,%3}, {%4,%5,%6,%7}, {%8,%9}, {%0,%1,%2,%3};" \
    : "+f"((c)[0]), "+f"((c)[1]), "+f"((c)[2]), "+f"((c)[3]) \
    : "r"((a)[0]), "r"((a)[1]), "r"((a)[2]), "r"((a)[3]), "r"(b0), "r"(b1))

#define CP16(so, ga) asm volatile("cp.async.cg.shared.global [%0], [%1], 16;" \
    :: "r"(so), "l"(ga) : "memory")
#define CP_COMMIT() asm volatile("cp.async.commit_group;" ::: "memory")
#define CP_WAIT1()  asm volatile("cp.async.wait_group 1;" ::: "memory")
#define CP_WAIT2()  asm volatile("cp.async.wait_group 2;" ::: "memory")

// packed f32x2 FMA
#define FFMA2(acc, a, b) asm("fma.rn.f32x2 %0, %1, %2, %0;" : "+l"(acc) : "l"(a), "l"(b))
#define PACK2(dst, lo, hi) asm("mov.b64 %0, {%1, %2};" : "=l"(dst) : "r"(lo), "r"(hi))
#define UNPACK2(lo, hi, src) asm("mov.b64 {%0, %1}, %2;" : "=r"(lo), "=r"(hi) : "l"(src))

// 64B-pitch tile with xor swizzle on 16B chunks
__device__ __forceinline__ uint32_t swz(uint32_t tile, int row, int chunk) {
    return tile + (uint32_t)row * 64u + ((uint32_t)((chunk ^ ((row >> 1) & 3)) & 3) << 4);
}

#define T64_B  4096u
#define T128_B 8192u

// QK: CTA 128x128, stage = 4 x 8KB = 32KB, 3 stages, 256 thr, 2 CTAs/SM
#define QK_STAGE_B 32768u
#define QK_SMEM    (3 * 32768)
// AV: CTA 64d x 128q, stage = Vhi(4K)+Phi(8K) = 12KB, 4 stages, 4 CTAs/SM
#define AV_STAGE_B 12288u
#define AV_SMEM    (4 * 12288)

// ---------------------------------------------------------------------------
// QK: S[128q,128k](fp32) = Q(128,256) . K(128,256)^T, 3-term split-fp16.
// 256 threads, 8 warps (4m x 2n), warp tile 32x64. 2 CTAs/SM. One batch/launch.
// ---------------------------------------------------------------------------
__global__ __launch_bounds__(256, 2) void qk_kernel(int bz)
{
    extern __shared__ __align__(128) char sm[];
    const int tid  = threadIdx.x;
    const int lane = tid & 31, wid = tid >> 5;
    const int wm = wid & 3, wn = wid >> 2;
    const int bx = blockIdx.x, by = blockIdx.y;

    size_t ab = ((size_t)bz * NN + (size_t)by * 128) * DD;
    size_t bb = ((size_t)bz * NN + (size_t)bx * 128) * DD;
    const __half* Ahi = g_Qhi + ab;  const __half* Alo = g_Qlo + ab;
    const __half* Bhi = g_Khi + bb;  const __half* Blo = g_Klo + bb;
    float* C = g_S + (size_t)bz * NN * NN + (size_t)by * 128 * NN + (size_t)bx * 128;

    const uint32_t sbase = smem_u32(sm);

    auto load_stage = [&](int s, int ch) {
        uint32_t st = sbase + (uint32_t)s * QK_STAGE_B;
        size_t k0 = (size_t)ch * 32;
        const __half* gt[4] = { Ahi + k0, Alo + k0, Bhi + k0, Blo + k0 };
        #pragma unroll
        for (int t2 = 0; t2 < 4; ++t2) {
            uint32_t tb = st + (uint32_t)t2 * T128_B;
            #pragma unroll
            for (int i = 0; i < 2; ++i) {
                int id = tid + i * 256;
                int row = id >> 2, c = id & 3;
                CP16(swz(tb, row, c), gt[t2] + (size_t)row * DD + c * 8);
            }
        }
    };

    float accf[2][8][4] = {};

    auto compute = [&](int s) {
        uint32_t st  = sbase + (uint32_t)s * QK_STAGE_B;
        uint32_t tAh = st, tAl = st + T128_B;
        uint32_t tBh = st + 2 * T128_B, tBl = st + 3 * T128_B;
        #pragma unroll
        for (int ks = 0; ks < 2; ++ks) {
            uint32_t ah[2][4], al[2][4];
            const int arow = wm * 32 + (lane & 15);
            const int achk = ks * 2 + (lane >> 4);
            #pragma unroll
            for (int mt = 0; mt < 2; ++mt) {
                LDM4(ah[mt], swz(tAh, arow + mt * 16, achk));
                LDM4(al[mt], swz(tAl, arow + mt * 16, achk));
            }
            const int brow = wn * 64 + ((lane >> 4) << 3) + (lane & 7);
            const int bchk = ks * 2 + ((lane >> 3) & 1);
            #pragma unroll
            for (int nt = 0; nt < 4; ++nt) {
                uint32_t bh4[4], bl4[4];
                LDM4(bh4, swz(tBh, brow + nt * 16, bchk));
                LDM4(bl4, swz(tBl, brow + nt * 16, bchk));
                #pragma unroll
                for (int mt = 0; mt < 2; ++mt) {
                    MMA16816F(accf[mt][nt*2],   ah[mt], bh4[0], bh4[1]);
                    MMA16816F(accf[mt][nt*2],   ah[mt], bl4[0], bl4[1]);
                    MMA16816F(accf[mt][nt*2],   al[mt], bh4[0], bh4[1]);
                    MMA16816F(accf[mt][nt*2+1], ah[mt], bh4[2], bh4[3]);
                    MMA16816F(accf[mt][nt*2+1], ah[mt], bl4[2], bl4[3]);
                    MMA16816F(accf[mt][nt*2+1], al[mt], bh4[2], bh4[3]);
                }
            }
        }
    };

    load_stage(0, 0); CP_COMMIT();
    load_stage(1, 1); CP_COMMIT();

    const int nchunks = DD / 32;  // 8
    for (int ch = 0; ch < nchunks; ++ch) {
        CP_WAIT1();
        __syncthreads();
        if (ch + 2 < nchunks) load_stage((ch + 2) % 3, ch + 2);
        CP_COMMIT();
        compute(ch % 3);
    }

    const int r0 = wm * 32 + (lane >> 2);
    const int c0 = wn * 64 + (lane & 3) * 2;
    #pragma unroll
    for (int mt = 0; mt < 2; ++mt)
        #pragma unroll
        for (int n8 = 0; n8 < 8; ++n8) {
            float* p = C + (size_t)(r0 + mt * 16) * NN + c0 + n8 * 8;
            *(float2*)p            = make_float2(accf[mt][n8][0], accf[mt][n8][1]);
            *(float2*)(p + 8 * NN) = make_float2(accf[mt][n8][2], accf[mt][n8][3]);
        }
}

// ---------------------------------------------------------------------------
// AV: out[64d,128q](fp32) = Vhi(64,4096) . P_un(128,4096)^T, scaled by invsum.
// Single-term. 128 threads, 4 warps (2m x 2n), warp tile 32d x 64q.
// 4 CTAs/SM, 512 CTAs = one full resident wave.
// ---------------------------------------------------------------------------
__global__ __launch_bounds__(128, 4) void av_kernel(float* __restrict__ outp)
{
    extern __shared__ __align__(128) char sm[];
    const int tid  = threadIdx.x;
    const int lane = tid & 31, wid = tid >> 5;
    const int wm = wid & 1, wn = wid >> 1;
    const int bx = blockIdx.x, by = blockIdx.y, bz = blockIdx.z;

    size_t ab = (size_t)bz * DD * NN + (size_t)by * 64 * NN;
    size_t bb = (size_t)bz * NN * NN + (size_t)bx * 128 * NN;
    const __half* Ahi = g_Vthi + ab;
    const __half* Bhi = g_Phi  + bb;
    float* C = outp + (size_t)bz * DD * NN + (size_t)by * 64 * NN + (size_t)bx * 128;
    const float* isum = g_invsum + (size_t)bz * NN + (size_t)bx * 128;

    const uint32_t sbase = smem_u32(sm);

    auto load_stage = [&](int s, int ch) {
        uint32_t st = sbase + (uint32_t)s * AV_STAGE_B;
        size_t k0 = (size_t)ch * 32;
        // V: 64 rows x 4 chunks = 256 -> 2/thread
        #pragma unroll
        for (int i = 0; i < 2; ++i) {
            int id = tid + i * 128;
            int row = id >> 2, c = id & 3;
            CP16(swz(st, row, c), Ahi + k0 + (size_t)row * NN + c * 8);
        }
        // P: 128 rows x 4 chunks = 512 -> 4/thread
        uint32_t tb = st + T64_B;
        #pragma unroll
        for (int i = 0; i < 4; ++i) {
            int id = tid + i * 128;
            int row = id >> 2, c = id & 3;
            CP16(swz(tb, row, c), Bhi + k0 + (size_t)row * NN + c * 8);
        }
    };

    float accf[2][8][4] = {};

    auto compute = [&](int s) {
        uint32_t st  = sbase + (uint32_t)s * AV_STAGE_B;
        uint32_t tAh = st;
        uint32_t tBh = st + T64_B;
        #pragma unroll
        for (int ks = 0; ks < 2; ++ks) {
            uint32_t ah[2][4];
            const int arow = wm * 32 + (lane & 15);
            const int achk = ks * 2 + (lane >> 4);
            #pragma unroll
            for (int mt = 0; mt < 2; ++mt)
                LDM4(ah[mt], swz(tAh, arow + mt * 16, achk));
            const int brow = wn * 64 + ((lane >> 4) << 3) + (lane & 7);
            const int bchk = ks * 2 + ((lane >> 3) & 1);
            #pragma unroll
            for (int nt = 0; nt < 4; ++nt) {
                uint32_t bh4[4];
                LDM4(bh4, swz(tBh, brow + nt * 16, bchk));
                #pragma unroll
                for (int mt = 0; mt < 2; ++mt) {
                    MMA16816F(accf[mt][nt*2],   ah[mt], bh4[0], bh4[1]);
                    MMA16816F(accf[mt][nt*2+1], ah[mt], bh4[2], bh4[3]);
                }
            }
        }
    };

    load_stage(0, 0); CP_COMMIT();
    load_stage(1, 1); CP_COMMIT();
    load_stage(2, 2); CP_COMMIT();

    const int nchunks = NN / 32;  // 128
    for (int ch = 0; ch < nchunks; ++ch) {
        CP_WAIT2();
        __syncthreads();
        if (ch + 3 < nchunks) load_stage((ch + 3) & 3, ch + 3);
        CP_COMMIT();
        compute(ch & 3);
    }

    const int r0 = wm * 32 + (lane >> 2);
    const int c0 = wn * 64 + (lane & 3) * 2;
    #pragma unroll
    for (int mt = 0; mt < 2; ++mt)
        #pragma unroll
        for (int n8 = 0; n8 < 8; ++n8) {
            float2 iv = *(const float2*)(isum + c0 + n8 * 8);
            float* p = C + (size_t)(r0 + mt * 16) * NN + c0 + n8 * 8;
            *(float2*)p            = make_float2(accf[mt][n8][0] * iv.x, accf[mt][n8][1] * iv.y);
            *(float2*)(p + 8 * NN) = make_float2(accf[mt][n8][2] * iv.x, accf[mt][n8][3] * iv.y);
        }
}

// ---------------------------------------------------------------------------
__device__ __forceinline__ void split8h(const float* v, uint4& uh, uint4& ul) {
    __half2 h[4], l[4];
    #pragma unroll
    for (int j = 0; j < 4; ++j) {
        float a = v[2*j], b = v[2*j+1];
        __half ha = __float2half_rn(a), hb = __float2half_rn(b);
        __half la = __float2half_rn(a - __half2float(ha));
        __half lb = __float2half_rn(b - __half2float(hb));
        h[j] = __halves2half2(ha, hb);
        l[j] = __halves2half2(la, lb);
    }
    uh = *(uint4*)h; ul = *(uint4*)l;
}

// Kernel 1: fused QKV projection (FFMA2), fp16 out.
// vmode 0: z in [0, 2*BB) -> Q/K hi+lo.  vmode 1: z in [0, BB) -> V hi only.
__global__ __launch_bounds__(256, 2) void proj_kernel(
    int vmode,
    const float* __restrict__ x,
    const float* __restrict__ Wq, const float* __restrict__ bq,
    const float* __restrict__ Wk, const float* __restrict__ bk,
    const float* __restrict__ Wv, const float* __restrict__ bv)
{
    __shared__ float As[16][132];
    __shared__ float Bs[16][132];

    const int bzz = blockIdx.z;
    const int b = vmode ? bzz : (bzz >> 1);
    const int w = vmode ? 2 : (bzz & 1);
    const float* W    = (w == 0) ? Wq : ((w == 1) ? Wk : Wv);
    const float* bias = (w == 0) ? bq : ((w == 1) ? bk : bv);

    const int m0 = blockIdx.x * 128;
    const int d0 = blockIdx.y * 128;
    const int tid = threadIdx.x;
    const int tx = tid & 15, ty = tid >> 4;
    const float* Abase = x + (size_t)b * DD * NN;

    unsigned long long acc2[8][4];
    #pragma unroll
    for (int i = 0; i < 8; ++i)
        #pragma unroll
        for (int j = 0; j < 4; ++j) acc2[i][j] = 0ull;

    float4 pa[2], pb[2];
    #pragma unroll
    for (int u = 0; u < 2; ++u) {
        int idx = tid + u * 256;
        int kl = idx >> 5, m4 = (idx & 31) << 2;
        pa[u] = *(const float4*)(Abase + (size_t)kl * NN + m0 + m4);
        pb[u] = *(const float4*)(W     + (size_t)kl * DD + d0 + m4);
    }
    for (int kc = 0; kc < DD; kc += 16) {
        #pragma unroll
        for (int u = 0; u < 2; ++u) {
            int idx = tid + u * 256;
            int kl = idx >> 5, m4 = (idx & 31) << 2;
            *(float4*)&As[kl][m4] = pa[u];
            *(float4*)&Bs[kl][m4] = pb[u];
        }
        __syncthreads();
        if (kc + 16 < DD) {
            int kn = kc + 16;
            #pragma unroll
            for (int u = 0; u < 2; ++u) {
                int idx = tid + u * 256;
                int kl = idx >> 5, m4 = (idx & 31) << 2;
                pa[u] = *(const float4*)(Abase + (size_t)(kn + kl) * NN + m0 + m4);
                pb[u] = *(const float4*)(W     + (size_t)(kn + kl) * DD + d0 + m4);
            }
        }
        #pragma unroll
        for (int kk = 0; kk < 16; ++kk) {
            float a[8], bb[8];
            *(float4*)&a[0]  = *(float4*)&As[kk][ty * 8];
            *(float4*)&a[4]  = *(float4*)&As[kk][ty * 8 + 4];
            *(float4*)&bb[0] = *(float4*)&Bs[kk][tx * 8];
            *(float4*)&bb[4] = *(float4*)&Bs[kk][tx * 8 + 4];
            unsigned long long b2[4];
            #pragma unroll
            for (int j = 0; j < 4; ++j)
                PACK2(b2[j], __float_as_uint(bb[2*j]), __float_as_uint(bb[2*j+1]));
            #pragma unroll
            for (int i = 0; i < 8; ++i) {
                unsigned long long a2;
                PACK2(a2, __float_as_uint(a[i]), __float_as_uint(a[i]));
                #pragma unroll
                for (int j = 0; j < 4; ++j)
                    FFMA2(acc2[i][j], a2, b2[j]);
            }
        }
        __syncthreads();
    }

    float acc[8][8];
    #pragma unroll
    for (int i = 0; i < 8; ++i)
        #pragma unroll
        for (int j = 0; j < 4; ++j) {
            uint32_t lo, hi;
            UNPACK2(lo, hi, acc2[i][j]);
            acc[i][2*j]   = __uint_as_float(lo);
            acc[i][2*j+1] = __uint_as_float(hi);
        }

    if (w < 2) {  // Q/K row-major [n][d], hi+lo
        __half* Oh = ((w == 0) ? g_Qhi : g_Khi) + (size_t)b * NN * DD;
        __half* Ol = ((w == 0) ? g_Qlo : g_Klo) + (size_t)b * NN * DD;
        #pragma unroll
        for (int i = 0; i < 8; ++i) {
            int n = m0 + ty * 8 + i, d = d0 + tx * 8;
            float v[8];
            #pragma unroll
            for (int j = 0; j < 8; ++j) v[j] = acc[i][j] + bias[d + j];
            uint4 uh, ul; split8h(v, uh, ul);
            *(uint4*)(Oh + (size_t)n * DD + d) = uh;
            *(uint4*)(Ol + (size_t)n * DD + d) = ul;
        }
    } else {      // V transposed [d][n], hi only
        __half* Oh = g_Vthi + (size_t)b * DD * NN;
        #pragma unroll
        for (int j = 0; j < 8; ++j) {
            int d = d0 + tx * 8 + j;
            float bb = bias[d];
            __half2 hv[4];
            #pragma unroll
            for (int i = 0; i < 4; ++i)
                hv[i] = __halves2half2(__float2half_rn(acc[2*i][j] + bb),
                                       __float2half_rn(acc[2*i+1][j] + bb));
            *(uint4*)(Oh + (size_t)d * NN + m0 + ty * 8) = *(uint4*)hv;
        }
    }
}

// Kernel 3: row softmax, fp32 S in, UNNORMALIZED fp16 exp out + invsum.
__inline__ __device__ float warpMax(float v) {
    #pragma unroll
    for (int o = 16; o; o >>= 1) v = fmaxf(v, __shfl_xor_sync(0xffffffffu, v, o));
    return v;
}
__inline__ __device__ float warpSum(float v) {
    #pragma unroll
    for (int o = 16; o; o >>= 1) v += __shfl_xor_sync(0xffffffffu, v, o);
    return v;
}

__global__ __launch_bounds__(256) void softmax_kernel(int bbase)
{
    __shared__ float red[8];
    const size_t row = (size_t)bbase * NN + blockIdx.x;
    const float* p = g_S + row * (size_t)NN;
    __half* ph = g_Phi + row * (size_t)NN;
    const int tid = threadIdx.x;
    const int lane = tid & 31, wid = tid >> 5;

    float4 v[4];
    float m = -CUDART_INF_F;
    #pragma unroll
    for (int u = 0; u < 4; ++u) {
        v[u] = *(const float4*)(p + (size_t)(tid + u * 256) * 4);
        m = fmaxf(m, fmaxf(fmaxf(v[u].x, v[u].y), fmaxf(v[u].z, v[u].w)));
    }
    m = warpMax(m);
    if (lane == 0) red[wid] = m;
    __syncthreads();
    float bm = red[0];
    #pragma unroll
    for (int i = 1; i < 8; ++i) bm = fmaxf(bm, red[i]);
    __syncthreads();

    float s = 0.f;
    #pragma unroll
    for (int u = 0; u < 4; ++u) {
        v[u].x = __expf(v[u].x - bm); v[u].y = __expf(v[u].y - bm);
        v[u].z = __expf(v[u].z - bm); v[u].w = __expf(v[u].w - bm);
        s += v[u].x + v[u].y + v[u].z + v[u].w;
    }
    s = warpSum(s);
    if (lane == 0) red[wid] = s;
    __syncthreads();
    float tot = 0.f;
    #pragma unroll
    for (int i = 0; i < 8; ++i) tot += red[i];
    if (tid == 0) g_invsum[row] = 1.0f / tot;

    #pragma unroll
    for (int u = 0; u < 4; ++u) {
        size_t idx = (size_t)(tid + u * 256) * 4;
        *(__half2*)(ph + idx)     = __halves2half2(__float2half_rn(v[u].x),
                                                   __float2half_rn(v[u].y));
        *(__half2*)(ph + idx + 2) = __halves2half2(__float2half_rn(v[u].z),
                                                   __float2half_rn(v[u].w));
    }
}

// ---------------------------------------------------------------------------
extern "C" void kernel_launch(void* const* d_in, const int* in_sizes, int n_in,
                              void* d_out, int out_size)
{
    const float* x  = (const float*)d_in[0];
    const float* Wq = (const float*)d_in[1];
    const float* bq = (const float*)d_in[2];
    const float* Wk = (const float*)d_in[3];
    const float* bk = (const float*)d_in[4];
    const float* Wv = (const float*)d_in[5];
    const float* bv = (const float*)d_in[6];
    float* out = (float*)d_out;

    static cudaStream_t s2 = nullptr;
    static cudaEvent_t eRoot, eQ[BB], eS;
    if (!s2) {
        cudaStreamCreateWithFlags(&s2, cudaStreamNonBlocking);
        cudaEventCreateWithFlags(&eRoot, cudaEventDisableTiming);
        for (int b = 0; b < BB; ++b) cudaEventCreateWithFlags(&eQ[b], cudaEventDisableTiming);
        cudaEventCreateWithFlags(&eS, cudaEventDisableTiming);
        cudaFuncSetAttribute(qk_kernel, cudaFuncAttributeMaxDynamicSharedMemorySize, QK_SMEM);
        cudaFuncSetAttribute(av_kernel, cudaFuncAttributeMaxDynamicSharedMemorySize, AV_SMEM);
    }

    // Legal fork: s2 joins capture via eRoot before any s2 work/events.
    cudaEventRecord(eRoot, 0);
    cudaStreamWaitEvent(s2, eRoot, 0);

    // s2: projV -> per-batch: (wait eQ[b]) softmax(b); eS after last.
    // s0: projQK(all) -> QK(b0..b3) -> (wait eS) AV(all batches, 1 wave).
    proj_kernel<<<dim3(NN / 128, DD / 128, BB), 256, 0, s2>>>(1, x, Wq, bq, Wk, bk, Wv, bv);

    proj_kernel<<<dim3(NN / 128, DD / 128, 2 * BB), 256>>>(0, x, Wq, bq, Wk, bk, Wv, bv);
    for (int b = 0; b < BB; ++b) {
        qk_kernel<<<dim3(NN / 128, NN / 128, 1), 256, QK_SMEM>>>(b);
        cudaEventRecord(eQ[b], 0);
        cudaStreamWaitEvent(s2, eQ[b], 0);
        softmax_kernel<<<NN, 256, 0, s2>>>(b);
    }
    cudaEventRecord(eS, s2);

    cudaStreamWaitEvent(0, eS, 0);
    av_kernel<<<dim3(NN / 128, DD / 64, BB), 128, AV_SMEM>>>(out);
}

// round 17
// speedup vs baseline: 1.1880x; 1.0278x over previous
#include <cuda_runtime.h>
#include <cuda_fp16.h>
#include <math_constants.h>
#include <cstdint>

#define BB 4
#define NN 4096
#define DD 256

// ---------------- device scratch (allocation-free rule) ----------------
__device__ __align__(128) __half g_Qhi[(size_t)BB*NN*DD];   // [b][n][d]
__device__ __align__(128) __half g_Qlo[(size_t)BB*NN*DD];
__device__ __align__(128) __half g_Khi[(size_t)BB*NN*DD];   // [b][n][d]
__device__ __align__(128) __half g_Klo[(size_t)BB*NN*DD];
__device__ __align__(128) __half g_Vthi[(size_t)BB*DD*NN];  // [b][d][key]
__device__ __align__(128) __half g_Phi[(size_t)BB*NN*NN];   // [b][q][key]  (UNNORMALIZED exp)
__device__ __align__(128) float  g_S [(size_t)BB*NN*NN];    // [b][q][key]
__device__ __align__(128) float  g_invsum[(size_t)BB*NN];   // 1/rowsum

// ---------------- helpers ----------------
__device__ __forceinline__ uint32_t smem_u32(const void* p) {
    uint32_t a;
    asm("{ .reg .u64 t; cvta.to.shared.u64 t, %1; cvt.u32.u64 %0, t; }" : "=r"(a) : "l"(p));
    return a;
}

#define LDM4(r, addr) asm volatile( \
    "ldmatrix.sync.aligned.m8n8.x4.shared.b16 {%0,%1,%2,%3}, [%4];" \
    : "=r"((r)[0]), "=r"((r)[1]), "=r"((r)[2]), "=r"((r)[3]) : "r"(addr))

#define MMA16816F(c, a, b0, b1) asm volatile( \
    "mma.sync.aligned.m16n8k16.row.col.f32.f16.f16.f32 " \
    "{%0,%1,%2,%3}, {%4,%5,%6,%7}, {%8,%9}, {%0,%1,%2,%3};" \
    : "+f"((c)[0]), "+f"((c)[1]), "+f"((c)[2]), "+f"((c)[3]) \
    : "r"((a)[0]), "r"((a)[1]), "r"((a)[2]), "r"((a)[3]), "r"(b0), "r"(b1))

#define CP16(so, ga) asm volatile("cp.async.cg.shared.global [%0], [%1], 16;" \
    :: "r"(so), "l"(ga) : "memory")
#define CP_COMMIT() asm volatile("cp.async.commit_group;" ::: "memory")
#define CP_WAIT1()  asm volatile("cp.async.wait_group 1;" ::: "memory")
#define CP_WAIT2()  asm volatile("cp.async.wait_group 2;" ::: "memory")

// packed f32x2 FMA
#define FFMA2(acc, a, b) asm("fma.rn.f32x2 %0, %1, %2, %0;" : "+l"(acc) : "l"(a), "l"(b))
#define PACK2(dst, lo, hi) asm("mov.b64 %0, {%1, %2};" : "=l"(dst) : "r"(lo), "r"(hi))
#define UNPACK2(lo, hi, src) asm("mov.b64 {%0, %1}, %2;" : "=r"(lo), "=r"(hi) : "l"(src))

// 64B-pitch tile with xor swizzle on 16B chunks
__device__ __forceinline__ uint32_t swz(uint32_t tile, int row, int chunk) {
    return tile + (uint32_t)row * 64u + ((uint32_t)((chunk ^ ((row >> 1) & 3)) & 3) << 4);
}

#define T64_B  4096u
#define T128_B 8192u

// QK: CTA 128x128, stage = 4 x 8KB = 32KB, 3 stages, 256 thr, 2 CTAs/SM
#define QK_STAGE_B 32768u
#define QK_SMEM    (3 * 32768)
// AV: CTA 64d x 128q, stage = Vhi(4K)+Phi(8K) = 12KB, 4 stages, 4 CTAs/SM
#define AV_STAGE_B 12288u
#define AV_SMEM    (4 * 12288)

// ---------------------------------------------------------------------------
// QK: S[128q,128k](fp32) = Q(128,256) . K(128,256)^T, 3-term split-fp16.
// 256 threads, 8 warps (4m x 2n), warp tile 32x64. 2 CTAs/SM. One batch/launch.
// ---------------------------------------------------------------------------
__global__ __launch_bounds__(256, 2) void qk_kernel(int bz)
{
    extern __shared__ __align__(128) char sm[];
    const int tid  = threadIdx.x;
    const int lane = tid & 31, wid = tid >> 5;
    const int wm = wid & 3, wn = wid >> 2;
    const int bx = blockIdx.x, by = blockIdx.y;

    size_t ab = ((size_t)bz * NN + (size_t)by * 128) * DD;
    size_t bb = ((size_t)bz * NN + (size_t)bx * 128) * DD;
    const __half* Ahi = g_Qhi + ab;  const __half* Alo = g_Qlo + ab;
    const __half* Bhi = g_Khi + bb;  const __half* Blo = g_Klo + bb;
    float* C = g_S + (size_t)bz * NN * NN + (size_t)by * 128 * NN + (size_t)bx * 128;

    const uint32_t sbase = smem_u32(sm);

    auto load_stage = [&](int s, int ch) {
        uint32_t st = sbase + (uint32_t)s * QK_STAGE_B;
        size_t k0 = (size_t)ch * 32;
        const __half* gt[4] = { Ahi + k0, Alo + k0, Bhi + k0, Blo + k0 };
        #pragma unroll
        for (int t2 = 0; t2 < 4; ++t2) {
            uint32_t tb = st + (uint32_t)t2 * T128_B;
            #pragma unroll
            for (int i = 0; i < 2; ++i) {
                int id = tid + i * 256;
                int row = id >> 2, c = id & 3;
                CP16(swz(tb, row, c), gt[t2] + (size_t)row * DD + c * 8);
            }
        }
    };

    float accf[2][8][4] = {};

    auto compute = [&](int s) {
        uint32_t st  = sbase + (uint32_t)s * QK_STAGE_B;
        uint32_t tAh = st, tAl = st + T128_B;
        uint32_t tBh = st + 2 * T128_B, tBl = st + 3 * T128_B;
        #pragma unroll
        for (int ks = 0; ks < 2; ++ks) {
            uint32_t ah[2][4], al[2][4];
            const int arow = wm * 32 + (lane & 15);
            const int achk = ks * 2 + (lane >> 4);
            #pragma unroll
            for (int mt = 0; mt < 2; ++mt) {
                LDM4(ah[mt], swz(tAh, arow + mt * 16, achk));
                LDM4(al[mt], swz(tAl, arow + mt * 16, achk));
            }
            const int brow = wn * 64 + ((lane >> 4) << 3) + (lane & 7);
            const int bchk = ks * 2 + ((lane >> 3) & 1);
            #pragma unroll
            for (int nt = 0; nt < 4; ++nt) {
                uint32_t bh4[4], bl4[4];
                LDM4(bh4, swz(tBh, brow + nt * 16, bchk));
                LDM4(bl4, swz(tBl, brow + nt * 16, bchk));
                #pragma unroll
                for (int mt = 0; mt < 2; ++mt) {
                    MMA16816F(accf[mt][nt*2],   ah[mt], bh4[0], bh4[1]);
                    MMA16816F(accf[mt][nt*2],   ah[mt], bl4[0], bl4[1]);
                    MMA16816F(accf[mt][nt*2],   al[mt], bh4[0], bh4[1]);
                    MMA16816F(accf[mt][nt*2+1], ah[mt], bh4[2], bh4[3]);
                    MMA16816F(accf[mt][nt*2+1], ah[mt], bl4[2], bl4[3]);
                    MMA16816F(accf[mt][nt*2+1], al[mt], bh4[2], bh4[3]);
                }
            }
        }
    };

    load_stage(0, 0); CP_COMMIT();
    load_stage(1, 1); CP_COMMIT();

    const int nchunks = DD / 32;  // 8
    for (int ch = 0; ch < nchunks; ++ch) {
        CP_WAIT1();
        __syncthreads();
        if (ch + 2 < nchunks) load_stage((ch + 2) % 3, ch + 2);
        CP_COMMIT();
        compute(ch % 3);
    }

    const int r0 = wm * 32 + (lane >> 2);
    const int c0 = wn * 64 + (lane & 3) * 2;
    #pragma unroll
    for (int mt = 0; mt < 2; ++mt)
        #pragma unroll
        for (int n8 = 0; n8 < 8; ++n8) {
            float* p = C + (size_t)(r0 + mt * 16) * NN + c0 + n8 * 8;
            *(float2*)p            = make_float2(accf[mt][n8][0], accf[mt][n8][1]);
            *(float2*)(p + 8 * NN) = make_float2(accf[mt][n8][2], accf[mt][n8][3]);
        }
}

// ---------------------------------------------------------------------------
// AV: out[64d,128q](fp32) = Vhi(64,4096) . P_un(128,4096)^T, scaled by invsum.
// Single-term. 128 threads, 4 warps (2m x 2n), warp tile 32d x 64q.
// 4 CTAs/SM, 512 CTAs = one full resident wave.
// ---------------------------------------------------------------------------
__global__ __launch_bounds__(128, 4) void av_kernel(float* __restrict__ outp)
{
    extern __shared__ __align__(128) char sm[];
    const int tid  = threadIdx.x;
    const int lane = tid & 31, wid = tid >> 5;
    const int wm = wid & 1, wn = wid >> 1;
    const int bx = blockIdx.x, by = blockIdx.y, bz = blockIdx.z;

    size_t ab = (size_t)bz * DD * NN + (size_t)by * 64 * NN;
    size_t bb = (size_t)bz * NN * NN + (size_t)bx * 128 * NN;
    const __half* Ahi = g_Vthi + ab;
    const __half* Bhi = g_Phi  + bb;
    float* C = outp + (size_t)bz * DD * NN + (size_t)by * 64 * NN + (size_t)bx * 128;
    const float* isum = g_invsum + (size_t)bz * NN + (size_t)bx * 128;

    const uint32_t sbase = smem_u32(sm);

    auto load_stage = [&](int s, int ch) {
        uint32_t st = sbase + (uint32_t)s * AV_STAGE_B;
        size_t k0 = (size_t)ch * 32;
        #pragma unroll
        for (int i = 0; i < 2; ++i) {
            int id = tid + i * 128;
            int row = id >> 2, c = id & 3;
            CP16(swz(st, row, c), Ahi + k0 + (size_t)row * NN + c * 8);
        }
        uint32_t tb = st + T64_B;
        #pragma unroll
        for (int i = 0; i < 4; ++i) {
            int id = tid + i * 128;
            int row = id >> 2, c = id & 3;
            CP16(swz(tb, row, c), Bhi + k0 + (size_t)row * NN + c * 8);
        }
    };

    float accf[2][8][4] = {};

    auto compute = [&](int s) {
        uint32_t st  = sbase + (uint32_t)s * AV_STAGE_B;
        uint32_t tAh = st;
        uint32_t tBh = st + T64_B;
        #pragma unroll
        for (int ks = 0; ks < 2; ++ks) {
            uint32_t ah[2][4];
            const int arow = wm * 32 + (lane & 15);
            const int achk = ks * 2 + (lane >> 4);
            #pragma unroll
            for (int mt = 0; mt < 2; ++mt)
                LDM4(ah[mt], swz(tAh, arow + mt * 16, achk));
            const int brow = wn * 64 + ((lane >> 4) << 3) + (lane & 7);
            const int bchk = ks * 2 + ((lane >> 3) & 1);
            #pragma unroll
            for (int nt = 0; nt < 4; ++nt) {
                uint32_t bh4[4];
                LDM4(bh4, swz(tBh, brow + nt * 16, bchk));
                #pragma unroll
                for (int mt = 0; mt < 2; ++mt) {
                    MMA16816F(accf[mt][nt*2],   ah[mt], bh4[0], bh4[1]);
                    MMA16816F(accf[mt][nt*2+1], ah[mt], bh4[2], bh4[3]);
                }
            }
        }
    };

    load_stage(0, 0); CP_COMMIT();
    load_stage(1, 1); CP_COMMIT();
    load_stage(2, 2); CP_COMMIT();

    const int nchunks = NN / 32;  // 128
    for (int ch = 0; ch < nchunks; ++ch) {
        CP_WAIT2();
        __syncthreads();
        if (ch + 3 < nchunks) load_stage((ch + 3) & 3, ch + 3);
        CP_COMMIT();
        compute(ch & 3);
    }

    const int r0 = wm * 32 + (lane >> 2);
    const int c0 = wn * 64 + (lane & 3) * 2;
    #pragma unroll
    for (int mt = 0; mt < 2; ++mt)
        #pragma unroll
        for (int n8 = 0; n8 < 8; ++n8) {
            float2 iv = *(const float2*)(isum + c0 + n8 * 8);
            float* p = C + (size_t)(r0 + mt * 16) * NN + c0 + n8 * 8;
            *(float2*)p            = make_float2(accf[mt][n8][0] * iv.x, accf[mt][n8][1] * iv.y);
            *(float2*)(p + 8 * NN) = make_float2(accf[mt][n8][2] * iv.x, accf[mt][n8][3] * iv.y);
        }
}

// ---------------------------------------------------------------------------
__device__ __forceinline__ void split8h(const float* v, uint4& uh, uint4& ul) {
    __half2 h[4], l[4];
    #pragma unroll
    for (int j = 0; j < 4; ++j) {
        float a = v[2*j], b = v[2*j+1];
        __half ha = __float2half_rn(a), hb = __float2half_rn(b);
        __half la = __float2half_rn(a - __half2float(ha));
        __half lb = __float2half_rn(b - __half2float(hb));
        h[j] = __halves2half2(ha, hb);
        l[j] = __halves2half2(la, lb);
    }
    uh = *(uint4*)h; ul = *(uint4*)l;
}

// Kernel 1: fused QKV projection (FFMA2), fp16 out.
// vmode 0: z in [0, 2*nb) -> b = bbase + z/2, w = z&1 (Q/K, hi+lo).
// vmode 1: z in [0, BB) -> V hi only.
__global__ __launch_bounds__(256, 2) void proj_kernel(
    int vmode, int bbase,
    const float* __restrict__ x,
    const float* __restrict__ Wq, const float* __restrict__ bq,
    const float* __restrict__ Wk, const float* __restrict__ bk,
    const float* __restrict__ Wv, const float* __restrict__ bv)
{
    __shared__ float As[16][132];
    __shared__ float Bs[16][132];

    const int bzz = blockIdx.z;
    const int b = vmode ? bzz : (bbase + (bzz >> 1));
    const int w = vmode ? 2 : (bzz & 1);
    const float* W    = (w == 0) ? Wq : ((w == 1) ? Wk : Wv);
    const float* bias = (w == 0) ? bq : ((w == 1) ? bk : bv);

    const int m0 = blockIdx.x * 128;
    const int d0 = blockIdx.y * 128;
    const int tid = threadIdx.x;
    const int tx = tid & 15, ty = tid >> 4;
    const float* Abase = x + (size_t)b * DD * NN;

    unsigned long long acc2[8][4];
    #pragma unroll
    for (int i = 0; i < 8; ++i)
        #pragma unroll
        for (int j = 0; j < 4; ++j) acc2[i][j] = 0ull;

    float4 pa[2], pb[2];
    #pragma unroll
    for (int u = 0; u < 2; ++u) {
        int idx = tid + u * 256;
        int kl = idx >> 5, m4 = (idx & 31) << 2;
        pa[u] = *(const float4*)(Abase + (size_t)kl * NN + m0 + m4);
        pb[u] = *(const float4*)(W     + (size_t)kl * DD + d0 + m4);
    }
    for (int kc = 0; kc < DD; kc += 16) {
        #pragma unroll
        for (int u = 0; u < 2; ++u) {
            int idx = tid + u * 256;
            int kl = idx >> 5, m4 = (idx & 31) << 2;
            *(float4*)&As[kl][m4] = pa[u];
            *(float4*)&Bs[kl][m4] = pb[u];
        }
        __syncthreads();
        if (kc + 16 < DD) {
            int kn = kc + 16;
            #pragma unroll
            for (int u = 0; u < 2; ++u) {
                int idx = tid + u * 256;
                int kl = idx >> 5, m4 = (idx & 31) << 2;
                pa[u] = *(const float4*)(Abase + (size_t)(kn + kl) * NN + m0 + m4);
                pb[u] = *(const float4*)(W     + (size_t)(kn + kl) * DD + d0 + m4);
            }
        }
        #pragma unroll
        for (int kk = 0; kk < 16; ++kk) {
            float a[8], bb[8];
            *(float4*)&a[0]  = *(float4*)&As[kk][ty * 8];
            *(float4*)&a[4]  = *(float4*)&As[kk][ty * 8 + 4];
            *(float4*)&bb[0] = *(float4*)&Bs[kk][tx * 8];
            *(float4*)&bb[4] = *(float4*)&Bs[kk][tx * 8 + 4];
            unsigned long long b2[4];
            #pragma unroll
            for (int j = 0; j < 4; ++j)
                PACK2(b2[j], __float_as_uint(bb[2*j]), __float_as_uint(bb[2*j+1]));
            #pragma unroll
            for (int i = 0; i < 8; ++i) {
                unsigned long long a2;
                PACK2(a2, __float_as_uint(a[i]), __float_as_uint(a[i]));
                #pragma unroll
                for (int j = 0; j < 4; ++j)
                    FFMA2(acc2[i][j], a2, b2[j]);
            }
        }
        __syncthreads();
    }

    float acc[8][8];
    #pragma unroll
    for (int i = 0; i < 8; ++i)
        #pragma unroll
        for (int j = 0; j < 4; ++j) {
            uint32_t lo, hi;
            UNPACK2(lo, hi, acc2[i][j]);
            acc[i][2*j]   = __uint_as_float(lo);
            acc[i][2*j+1] = __uint_as_float(hi);
        }

    if (w < 2) {  // Q/K row-major [n][d], hi+lo
        __half* Oh = ((w == 0) ? g_Qhi : g_Khi) + (size_t)b * NN * DD;
        __half* Ol = ((w == 0) ? g_Qlo : g_Klo) + (size_t)b * NN * DD;
        #pragma unroll
        for (int i = 0; i < 8; ++i) {
            int n = m0 + ty * 8 + i, d = d0 + tx * 8;
            float v[8];
            #pragma unroll
            for (int j = 0; j < 8; ++j) v[j] = acc[i][j] + bias[d + j];
            uint4 uh, ul; split8h(v, uh, ul);
            *(uint4*)(Oh + (size_t)n * DD + d) = uh;
            *(uint4*)(Ol + (size_t)n * DD + d) = ul;
        }
    } else {      // V transposed [d][n], hi only
        __half* Oh = g_Vthi + (size_t)b * DD * NN;
        #pragma unroll
        for (int j = 0; j < 8; ++j) {
            int d = d0 + tx * 8 + j;
            float bb = bias[d];
            __half2 hv[4];
            #pragma unroll
            for (int i = 0; i < 4; ++i)
                hv[i] = __halves2half2(__float2half_rn(acc[2*i][j] + bb),
                                       __float2half_rn(acc[2*i+1][j] + bb));
            *(uint4*)(Oh + (size_t)d * NN + m0 + ty * 8) = *(uint4*)hv;
        }
    }
}

// Kernel 3: row softmax, fp32 S in, UNNORMALIZED fp16 exp out + invsum.
__inline__ __device__ float warpMax(float v) {
    #pragma unroll
    for (int o = 16; o; o >>= 1) v = fmaxf(v, __shfl_xor_sync(0xffffffffu, v, o));
    return v;
}
__inline__ __device__ float warpSum(float v) {
    #pragma unroll
    for (int o = 16; o; o >>= 1) v += __shfl_xor_sync(0xffffffffu, v, o);
    return v;
}

__global__ __launch_bounds__(256) void softmax_kernel(int bbase)
{
    __shared__ float red[8];
    const size_t row = (size_t)bbase * NN + blockIdx.x;
    const float* p = g_S + row * (size_t)NN;
    __half* ph = g_Phi + row * (size_t)NN;
    const int tid = threadIdx.x;
    const int lane = tid & 31, wid = tid >> 5;

    float4 v[4];
    float m = -CUDART_INF_F;
    #pragma unroll
    for (int u = 0; u < 4; ++u) {
        v[u] = *(const float4*)(p + (size_t)(tid + u * 256) * 4);
        m = fmaxf(m, fmaxf(fmaxf(v[u].x, v[u].y), fmaxf(v[u].z, v[u].w)));
    }
    m = warpMax(m);
    if (lane == 0) red[wid] = m;
    __syncthreads();
    float bm = red[0];
    #pragma unroll
    for (int i = 1; i < 8; ++i) bm = fmaxf(bm, red[i]);
    __syncthreads();

    float s = 0.f;
    #pragma unroll
    for (int u = 0; u < 4; ++u) {
        v[u].x = __expf(v[u].x - bm); v[u].y = __expf(v[u].y - bm);
        v[u].z = __expf(v[u].z - bm); v[u].w = __expf(v[u].w - bm);
        s += v[u].x + v[u].y + v[u].z + v[u].w;
    }
    s = warpSum(s);
    if (lane == 0) red[wid] = s;
    __syncthreads();
    float tot = 0.f;
    #pragma unroll
    for (int i = 0; i < 8; ++i) tot += red[i];
    if (tid == 0) g_invsum[row] = 1.0f / tot;

    #pragma unroll
    for (int u = 0; u < 4; ++u) {
        size_t idx = (size_t)(tid + u * 256) * 4;
        *(__half2*)(ph + idx)     = __halves2half2(__float2half_rn(v[u].x),
                                                   __float2half_rn(v[u].y));
        *(__half2*)(ph + idx + 2) = __halves2half2(__float2half_rn(v[u].z),
                                                   __float2half_rn(v[u].w));
    }
}

// ---------------------------------------------------------------------------
extern "C" void kernel_launch(void* const* d_in, const int* in_sizes, int n_in,
                              void* d_out, int out_size)
{
    const float* x  = (const float*)d_in[0];
    const float* Wq = (const float*)d_in[1];
    const float* bq = (const float*)d_in[2];
    const float* Wk = (const float*)d_in[3];
    const float* bk = (const float*)d_in[4];
    const float* Wv = (const float*)d_in[5];
    const float* bv = (const float*)d_in[6];
    float* out = (float*)d_out;

    static cudaStream_t s2 = nullptr;
    static cudaEvent_t eRoot, eP, eQ[BB], eS;
    if (!s2) {
        cudaStreamCreateWithFlags(&s2, cudaStreamNonBlocking);
        cudaEventCreateWithFlags(&eRoot, cudaEventDisableTiming);
        cudaEventCreateWithFlags(&eP, cudaEventDisableTiming);
        for (int b = 0; b < BB; ++b) cudaEventCreateWithFlags(&eQ[b], cudaEventDisableTiming);
        cudaEventCreateWithFlags(&eS, cudaEventDisableTiming);
        cudaFuncSetAttribute(qk_kernel, cudaFuncAttributeMaxDynamicSharedMemorySize, QK_SMEM);
        cudaFuncSetAttribute(av_kernel, cudaFuncAttributeMaxDynamicSharedMemorySize, AV_SMEM);
    }

    // Legal fork: s2 joins capture via eRoot before any s2 work/events.
    cudaEventRecord(eRoot, 0);
    cudaStreamWaitEvent(s2, eRoot, 0);

    // s2: projV(all) -> projQK(b1..b3)[eP] -> per-batch (wait eQ[b]) softmax(b) -> eS
    // s0: projQK(b0) -> QK(b0) -> (wait eP) QK(b1..b3) -> (wait eS) AV(all, 1 wave)
    proj_kernel<<<dim3(NN / 128, DD / 128, BB), 256, 0, s2>>>(1, 0, x, Wq, bq, Wk, bk, Wv, bv);
    proj_kernel<<<dim3(NN / 128, DD / 128, 6), 256, 0, s2>>>(0, 1, x, Wq, bq, Wk, bk, Wv, bv);
    cudaEventRecord(eP, s2);

    proj_kernel<<<dim3(NN / 128, DD / 128, 2), 256>>>(0, 0, x, Wq, bq, Wk, bk, Wv, bv);
    qk_kernel<<<dim3(NN / 128, NN / 128, 1), 256, QK_SMEM>>>(0);
    cudaEventRecord(eQ[0], 0);
    cudaStreamWaitEvent(0, eP, 0);
    for (int b = 1; b < BB; ++b) {
        qk_kernel<<<dim3(NN / 128, NN / 128, 1), 256, QK_SMEM>>>(b);
        cudaEventRecord(eQ[b], 0);
    }
    for (int b = 0; b < BB; ++b) {
        cudaStreamWaitEvent(s2, eQ[b], 0);
        softmax_kernel<<<NN, 256, 0, s2>>>(b);
    }
    cudaEventRecord(eS, s2);

    cudaStreamWaitEvent(0, eS, 0);
    av_kernel<<<dim3(NN / 128, DD / 64, BB), 128, AV_SMEM>>>(out);
}